// round 1
// baseline (speedup 1.0000x reference)
#include <cuda_runtime.h>
#include <math.h>

#define NF 256     // input feature dim
#define NH 128     // hidden dim
#define NC 10      // classes
#define NMAX 50000
#define EMAX 800000

// Scratch (static device globals — no runtime allocation allowed)
__device__ float g_h[(size_t)NMAX * NH];     // GEMM output (pre-aggregation)
__device__ float g_agg[(size_t)NMAX * NH];   // aggregated output (pre-relu)
__device__ float g_coef[EMAX];               // per-edge norm coefficient
__device__ float g_deg[NMAX];                // weighted in-degree (incl. self loop)
__device__ float g_dinv[NMAX];               // deg^{-1/2}
__device__ float g_selfc[NMAX];              // dinv^2 (self-loop coefficient)

// ---------------------------------------------------------------------------
// Degree / normalization precompute
// ---------------------------------------------------------------------------
__global__ void init_deg_kernel(int n) {
    int i = blockIdx.x * blockDim.x + threadIdx.x;
    if (i < n) g_deg[i] = 1.0f;  // self-loop weight
}

__global__ void accum_deg_kernel(const int* __restrict__ dst,
                                 const float* __restrict__ ew, int E) {
    int e = blockIdx.x * blockDim.x + threadIdx.x;
    if (e < E) atomicAdd(&g_deg[dst[e]], ew[e]);
}

__global__ void dinv_kernel(int n) {
    int i = blockIdx.x * blockDim.x + threadIdx.x;
    if (i < n) {
        float d = g_deg[i];
        float r = (d > 0.0f) ? rsqrtf(d) : 0.0f;
        g_dinv[i] = r;
        g_selfc[i] = r * r;
    }
}

__global__ void coef_kernel(const int* __restrict__ src, const int* __restrict__ dst,
                            const float* __restrict__ ew, int E) {
    int e = blockIdx.x * blockDim.x + threadIdx.x;
    if (e < E) g_coef[e] = g_dinv[src[e]] * ew[e] * g_dinv[dst[e]];
}

// ---------------------------------------------------------------------------
// SGEMM: C[N x 128] = A[N x K] @ B[K x 128]  (optionally relu(A) on read)
// BM=128, BN=128, BK=8, 256 threads, 8x8 per thread
// ---------------------------------------------------------------------------
__global__ __launch_bounds__(256) void sgemm_bn128(const float* __restrict__ A,
                                                   const float* __restrict__ B,
                                                   float* __restrict__ Cm,
                                                   int N, int K, int reluA) {
    __shared__ float As[8][128];
    __shared__ float Bs[8][128];

    int tid = threadIdx.x;
    int row0 = blockIdx.x * 128;
    int ty = tid >> 4;   // 0..15 -> output rows ty*8..+8
    int tx = tid & 15;   // 0..15 -> output cols tx*8..+8

    float acc[8][8];
#pragma unroll
    for (int i = 0; i < 8; i++)
#pragma unroll
        for (int j = 0; j < 8; j++) acc[i][j] = 0.0f;

    int aRow = tid >> 1;         // 0..127
    int aK4  = (tid & 1) * 4;    // 0 or 4
    int bK   = tid >> 5;         // 0..7
    int bCol = (tid & 31) * 4;   // 0..124

    for (int kb = 0; kb < K; kb += 8) {
        // Load A tile (transposed into As[k][row]) with row guard + optional relu
        float4 av = make_float4(0.f, 0.f, 0.f, 0.f);
        int gr = row0 + aRow;
        if (gr < N)
            av = *reinterpret_cast<const float4*>(A + (size_t)gr * K + kb + aK4);
        if (reluA) {
            av.x = fmaxf(av.x, 0.f); av.y = fmaxf(av.y, 0.f);
            av.z = fmaxf(av.z, 0.f); av.w = fmaxf(av.w, 0.f);
        }
        As[aK4 + 0][aRow] = av.x;
        As[aK4 + 1][aRow] = av.y;
        As[aK4 + 2][aRow] = av.z;
        As[aK4 + 3][aRow] = av.w;

        // Load B tile
        float4 bv = *reinterpret_cast<const float4*>(B + (size_t)(kb + bK) * 128 + bCol);
        *reinterpret_cast<float4*>(&Bs[bK][bCol]) = bv;

        __syncthreads();

#pragma unroll
        for (int k = 0; k < 8; k++) {
            float4 a0 = *reinterpret_cast<const float4*>(&As[k][ty * 8]);
            float4 a1 = *reinterpret_cast<const float4*>(&As[k][ty * 8 + 4]);
            float4 b0 = *reinterpret_cast<const float4*>(&Bs[k][tx * 8]);
            float4 b1 = *reinterpret_cast<const float4*>(&Bs[k][tx * 8 + 4]);
            float a[8] = {a0.x, a0.y, a0.z, a0.w, a1.x, a1.y, a1.z, a1.w};
            float b[8] = {b0.x, b0.y, b0.z, b0.w, b1.x, b1.y, b1.z, b1.w};
#pragma unroll
            for (int i = 0; i < 8; i++)
#pragma unroll
                for (int j = 0; j < 8; j++) acc[i][j] = fmaf(a[i], b[j], acc[i][j]);
        }
        __syncthreads();
    }

#pragma unroll
    for (int i = 0; i < 8; i++) {
        int gr = row0 + ty * 8 + i;
        if (gr < N) {
            float4 c0 = make_float4(acc[i][0], acc[i][1], acc[i][2], acc[i][3]);
            float4 c1 = make_float4(acc[i][4], acc[i][5], acc[i][6], acc[i][7]);
            *reinterpret_cast<float4*>(Cm + (size_t)gr * 128 + tx * 8) = c0;
            *reinterpret_cast<float4*>(Cm + (size_t)gr * 128 + tx * 8 + 4) = c1;
        }
    }
}

// ---------------------------------------------------------------------------
// agg[i][:] = b[:] + h[i][:] * selfc[i]   (bias + self-loop term, float4)
// ---------------------------------------------------------------------------
__global__ void init_agg_kernel(const float* __restrict__ b, int n) {
    int t = blockIdx.x * blockDim.x + threadIdx.x;
    if (t >= n * 32) return;
    int i = t >> 5;
    int c = t & 31;
    float sc = g_selfc[i];
    float4 hv = reinterpret_cast<const float4*>(g_h)[t];
    float4 bv = reinterpret_cast<const float4*>(b)[c];
    float4 r;
    r.x = fmaf(hv.x, sc, bv.x);
    r.y = fmaf(hv.y, sc, bv.y);
    r.z = fmaf(hv.z, sc, bv.z);
    r.w = fmaf(hv.w, sc, bv.w);
    reinterpret_cast<float4*>(g_agg)[t] = r;
}

// ---------------------------------------------------------------------------
// Edge scatter: agg[dst] += coef[e] * h[src]   (warp per edge, v4 red)
// ---------------------------------------------------------------------------
__global__ void scatter_kernel(const int* __restrict__ src, const int* __restrict__ dst,
                               int E) {
    int t = blockIdx.x * blockDim.x + threadIdx.x;
    int e = t >> 5;
    if (e >= E) return;
    int c = t & 31;
    int s = __ldg(src + e);
    int d = __ldg(dst + e);
    float w = __ldg(g_coef + e);
    float4 v = reinterpret_cast<const float4*>(g_h)[(size_t)s * 32 + c];
    v.x *= w; v.y *= w; v.z *= w; v.w *= w;
    float4* ap = reinterpret_cast<float4*>(g_agg) + (size_t)d * 32 + c;
    asm volatile("red.global.add.v4.f32 [%0], {%1,%2,%3,%4};"
                 :: "l"(ap), "f"(v.x), "f"(v.y), "f"(v.z), "f"(v.w)
                 : "memory");
}

// ---------------------------------------------------------------------------
// FC + softmax: out[i] = softmax(relu(agg[i]) @ fc_w + fc_b)   (warp per node)
// ---------------------------------------------------------------------------
__global__ void fc_softmax_kernel(const float* __restrict__ fw,
                                  const float* __restrict__ fb,
                                  float* __restrict__ out, int n) {
    int warp = (blockIdx.x * blockDim.x + threadIdx.x) >> 5;
    int lane = threadIdx.x & 31;
    if (warp >= n) return;
    const float* hr = g_agg + (size_t)warp * NH;

    float acc[NC];
#pragma unroll
    for (int c = 0; c < NC; c++) acc[c] = 0.0f;
#pragma unroll
    for (int kk = 0; kk < 4; kk++) {
        int k = lane + kk * 32;
        float hv = fmaxf(hr[k], 0.0f);
#pragma unroll
        for (int c = 0; c < NC; c++) acc[c] = fmaf(hv, __ldg(fw + k * NC + c), acc[c]);
    }
#pragma unroll
    for (int c = 0; c < NC; c++) {
#pragma unroll
        for (int off = 16; off; off >>= 1)
            acc[c] += __shfl_xor_sync(0xffffffffu, acc[c], off);
        acc[c] += fb[c];
    }
    float mx = acc[0];
#pragma unroll
    for (int c = 1; c < NC; c++) mx = fmaxf(mx, acc[c]);
    float ex[NC];
    float sum = 0.0f;
#pragma unroll
    for (int c = 0; c < NC; c++) { ex[c] = __expf(acc[c] - mx); sum += ex[c]; }
    float inv = 1.0f / sum;
    if (lane < NC) out[(size_t)warp * NC + lane] = ex[lane] * inv;
}

// ---------------------------------------------------------------------------
// Launch
// ---------------------------------------------------------------------------
extern "C" void kernel_launch(void* const* d_in, const int* in_sizes, int n_in,
                              void* d_out, int out_size) {
    const float* x  = (const float*)d_in[0];
    const int*   ei = (const int*)d_in[1];
    const float* ew = (const float*)d_in[2];
    const float* W1 = (const float*)d_in[3];
    const float* b1 = (const float*)d_in[4];
    const float* W2 = (const float*)d_in[5];
    const float* b2 = (const float*)d_in[6];
    const float* W3 = (const float*)d_in[7];
    const float* b3 = (const float*)d_in[8];
    const float* fw = (const float*)d_in[9];
    const float* fb = (const float*)d_in[10];
    float* out = (float*)d_out;

    int N = in_sizes[0] / NF;
    int E = in_sizes[2];
    const int* src = ei;
    const int* dst = ei + E;

    float *hbuf, *aggbuf;
    cudaGetSymbolAddress((void**)&hbuf, g_h);
    cudaGetSymbolAddress((void**)&aggbuf, g_agg);

    const int T = 256;
    int gN  = (N + T - 1) / T;
    int gE  = (E + T - 1) / T;
    int gNF = (N * 32 + T - 1) / T;           // N*32 float4 threads
    int gES = ((E * 32) + T - 1) / T;         // warp per edge
    int gW  = (N * 32 + T - 1) / T;           // warp per node
    int gG  = (N + 127) / 128;

    // Normalization precompute (reused by all 3 layers)
    init_deg_kernel<<<gN, T>>>(N);
    accum_deg_kernel<<<gE, T>>>(dst, ew, E);
    dinv_kernel<<<gN, T>>>(N);
    coef_kernel<<<gE, T>>>(src, dst, ew, E);

    // Layer 1: h = x @ W1 ; agg = b1 + selfc*h ; agg += scatter(edges)
    sgemm_bn128<<<gG, T>>>(x, W1, hbuf, N, NF, 0);
    init_agg_kernel<<<gNF, T>>>(b1, N);
    scatter_kernel<<<gES, T>>>(src, dst, E);

    // Layer 2 (relu fused into GEMM A-read)
    sgemm_bn128<<<gG, T>>>(aggbuf, W2, hbuf, N, NH, 1);
    init_agg_kernel<<<gNF, T>>>(b2, N);
    scatter_kernel<<<gES, T>>>(src, dst, E);

    // Layer 3
    sgemm_bn128<<<gG, T>>>(aggbuf, W3, hbuf, N, NH, 1);
    init_agg_kernel<<<gNF, T>>>(b3, N);
    scatter_kernel<<<gES, T>>>(src, dst, E);

    // FC + softmax (relu fused)
    fc_softmax_kernel<<<gW, T>>>(fw, fb, out, N);
}

// round 2
// speedup vs baseline: 1.3412x; 1.3412x over previous
#include <cuda_runtime.h>
#include <math.h>

#define NF 256
#define NH 128
#define NC 10
#define NMAX 50000
#define EMAX 800000

// Scratch
__device__ float g_h[(size_t)NMAX * NH];
__device__ float g_agg[(size_t)NMAX * NH];
__device__ float g_deg[NMAX];
__device__ float g_dinv[NMAX];
__device__ float g_selfc[NMAX];
__device__ int   g_cnt[NMAX];
__device__ int   g_pos[NMAX];
__device__ int   g_rowoff[NMAX + 1];
__device__ int   g_csr_src[EMAX];
__device__ float g_csr_coef[EMAX];

// ---------------- f32x2 packed-FMA helpers -------------------------------
__device__ __forceinline__ unsigned long long pack2(float lo, float hi) {
    unsigned long long r;
    asm("mov.b64 %0,{%1,%2};" : "=l"(r) : "f"(lo), "f"(hi));
    return r;
}
__device__ __forceinline__ void fma2(unsigned long long& d, unsigned long long a,
                                     unsigned long long b) {
    asm("fma.rn.f32x2 %0,%1,%2,%0;" : "+l"(d) : "l"(a), "l"(b));
}
__device__ __forceinline__ float2 unpack2(unsigned long long v) {
    float2 r;
    asm("mov.b64 {%0,%1},%2;" : "=f"(r.x), "=f"(r.y) : "l"(v));
    return r;
}

// ---------------- degree / norm / CSR precompute -------------------------
__global__ void init_deg_kernel(int n) {
    int i = blockIdx.x * blockDim.x + threadIdx.x;
    if (i < n) { g_deg[i] = 1.0f; g_cnt[i] = 0; }
}

__global__ void accum_deg_kernel(const int* __restrict__ dst,
                                 const float* __restrict__ ew, int E) {
    int e = blockIdx.x * blockDim.x + threadIdx.x;
    if (e < E) {
        int d = dst[e];
        atomicAdd(&g_deg[d], ew[e]);
        atomicAdd(&g_cnt[d], 1);
    }
}

__global__ void dinv_kernel(int n) {
    int i = blockIdx.x * blockDim.x + threadIdx.x;
    if (i < n) {
        float d = g_deg[i];
        float r = (d > 0.0f) ? rsqrtf(d) : 0.0f;
        g_dinv[i] = r;
        g_selfc[i] = r * r;
    }
}

// single-block exclusive scan of g_cnt -> g_rowoff / g_pos
__global__ __launch_bounds__(1024) void scan_kernel(int n) {
    __shared__ int warpsum[32];
    __shared__ int carry_s;
    int tid = threadIdx.x, lane = tid & 31, wid = tid >> 5;
    if (tid == 0) carry_s = 0;
    __syncthreads();
    for (int base = 0; base < n; base += 1024) {
        int i = base + tid;
        int v = (i < n) ? g_cnt[i] : 0;
        int x = v;
#pragma unroll
        for (int off = 1; off < 32; off <<= 1) {
            int y = __shfl_up_sync(0xffffffffu, x, off);
            if (lane >= off) x += y;
        }
        if (lane == 31) warpsum[wid] = x;
        __syncthreads();
        if (wid == 0) {
            int s = warpsum[lane];
#pragma unroll
            for (int off = 1; off < 32; off <<= 1) {
                int y = __shfl_up_sync(0xffffffffu, s, off);
                if (lane >= off) s += y;
            }
            warpsum[lane] = s;
        }
        __syncthreads();
        int woff = wid ? warpsum[wid - 1] : 0;
        int carry = carry_s;
        int incl = x + woff + carry;
        if (i < n) {
            int excl = incl - v;
            g_rowoff[i] = excl;
            g_pos[i] = excl;
        }
        int chunk_total = warpsum[31];
        __syncthreads();
        if (tid == 0) carry_s = carry + chunk_total;
        __syncthreads();
    }
    if (threadIdx.x == 0) g_rowoff[n] = carry_s;
}

__global__ void fill_kernel(const int* __restrict__ src, const int* __restrict__ dst,
                            const float* __restrict__ ew, int E) {
    int e = blockIdx.x * blockDim.x + threadIdx.x;
    if (e < E) {
        int s = src[e], d = dst[e];
        int slot = atomicAdd(&g_pos[d], 1);
        g_csr_src[slot] = s;
        g_csr_coef[slot] = g_dinv[s] * ew[e] * g_dinv[d];
    }
}

// ---------------- SGEMM (f32x2 packed FMA), C[N x 128] = A[N x K] @ B ----
__global__ __launch_bounds__(256) void sgemm_bn128(const float* __restrict__ A,
                                                   const float* __restrict__ B,
                                                   float* __restrict__ Cm,
                                                   int N, int K, int reluA) {
    __shared__ __align__(16) float As[8][128];
    __shared__ __align__(16) float Bs[8][128];

    int tid = threadIdx.x;
    int row0 = blockIdx.x * 128;
    int ty = tid >> 4;
    int tx = tid & 15;

    unsigned long long acc[8][4];
#pragma unroll
    for (int i = 0; i < 8; i++)
#pragma unroll
        for (int j = 0; j < 4; j++) acc[i][j] = 0ull;

    int aRow = tid >> 1;
    int aK4  = (tid & 1) * 4;
    int bK   = tid >> 5;
    int bCol = (tid & 31) * 4;

    for (int kb = 0; kb < K; kb += 8) {
        float4 av = make_float4(0.f, 0.f, 0.f, 0.f);
        int gr = row0 + aRow;
        if (gr < N)
            av = *reinterpret_cast<const float4*>(A + (size_t)gr * K + kb + aK4);
        if (reluA) {
            av.x = fmaxf(av.x, 0.f); av.y = fmaxf(av.y, 0.f);
            av.z = fmaxf(av.z, 0.f); av.w = fmaxf(av.w, 0.f);
        }
        As[aK4 + 0][aRow] = av.x;
        As[aK4 + 1][aRow] = av.y;
        As[aK4 + 2][aRow] = av.z;
        As[aK4 + 3][aRow] = av.w;

        float4 bv = *reinterpret_cast<const float4*>(B + (size_t)(kb + bK) * 128 + bCol);
        *reinterpret_cast<float4*>(&Bs[bK][bCol]) = bv;

        __syncthreads();

#pragma unroll
        for (int k = 0; k < 8; k++) {
            float4 a0 = *reinterpret_cast<const float4*>(&As[k][ty * 8]);
            float4 a1 = *reinterpret_cast<const float4*>(&As[k][ty * 8 + 4]);
            ulonglong2 bp01 = *reinterpret_cast<const ulonglong2*>(&Bs[k][tx * 8]);
            ulonglong2 bp23 = *reinterpret_cast<const ulonglong2*>(&Bs[k][tx * 8 + 4]);
            float a[8] = {a0.x, a0.y, a0.z, a0.w, a1.x, a1.y, a1.z, a1.w};
#pragma unroll
            for (int i = 0; i < 8; i++) {
                unsigned long long ad = pack2(a[i], a[i]);
                fma2(acc[i][0], ad, bp01.x);
                fma2(acc[i][1], ad, bp01.y);
                fma2(acc[i][2], ad, bp23.x);
                fma2(acc[i][3], ad, bp23.y);
            }
        }
        __syncthreads();
    }

#pragma unroll
    for (int i = 0; i < 8; i++) {
        int gr = row0 + ty * 8 + i;
        if (gr < N) {
            float2 p0 = unpack2(acc[i][0]);
            float2 p1 = unpack2(acc[i][1]);
            float2 p2 = unpack2(acc[i][2]);
            float2 p3 = unpack2(acc[i][3]);
            float4 c0 = make_float4(p0.x, p0.y, p1.x, p1.y);
            float4 c1 = make_float4(p2.x, p2.y, p3.x, p3.y);
            *reinterpret_cast<float4*>(Cm + (size_t)gr * 128 + tx * 8) = c0;
            *reinterpret_cast<float4*>(Cm + (size_t)gr * 128 + tx * 8 + 4) = c1;
        }
    }
}

// ---------------- CSR gather aggregation (warp per node) -----------------
// agg[i] = b + selfc[i]*h[i] + sum_{e in in(i)} coef[e]*h[src[e]]
__global__ void gather_kernel(const float* __restrict__ b, int n) {
    int t = blockIdx.x * blockDim.x + threadIdx.x;
    int node = t >> 5;
    int lane = t & 31;
    if (node >= n) return;

    const float4* h4 = reinterpret_cast<const float4*>(g_h);
    float4 bv = reinterpret_cast<const float4*>(b)[lane];
    float sc = g_selfc[node];
    float4 hv = h4[(size_t)node * 32 + lane];
    float4 acc;
    acc.x = fmaf(hv.x, sc, bv.x);
    acc.y = fmaf(hv.y, sc, bv.y);
    acc.z = fmaf(hv.z, sc, bv.z);
    acc.w = fmaf(hv.w, sc, bv.w);

    int beg = g_rowoff[node];
    int end = g_rowoff[node + 1];
    int e = beg;
    for (; e + 1 < end; e += 2) {
        int s0 = __ldg(g_csr_src + e);
        int s1 = __ldg(g_csr_src + e + 1);
        float w0 = __ldg(g_csr_coef + e);
        float w1 = __ldg(g_csr_coef + e + 1);
        float4 v0 = h4[(size_t)s0 * 32 + lane];
        float4 v1 = h4[(size_t)s1 * 32 + lane];
        acc.x = fmaf(v0.x, w0, acc.x);
        acc.y = fmaf(v0.y, w0, acc.y);
        acc.z = fmaf(v0.z, w0, acc.z);
        acc.w = fmaf(v0.w, w0, acc.w);
        acc.x = fmaf(v1.x, w1, acc.x);
        acc.y = fmaf(v1.y, w1, acc.y);
        acc.z = fmaf(v1.z, w1, acc.z);
        acc.w = fmaf(v1.w, w1, acc.w);
    }
    if (e < end) {
        int s0 = __ldg(g_csr_src + e);
        float w0 = __ldg(g_csr_coef + e);
        float4 v0 = h4[(size_t)s0 * 32 + lane];
        acc.x = fmaf(v0.x, w0, acc.x);
        acc.y = fmaf(v0.y, w0, acc.y);
        acc.z = fmaf(v0.z, w0, acc.z);
        acc.w = fmaf(v0.w, w0, acc.w);
    }
    reinterpret_cast<float4*>(g_agg)[(size_t)node * 32 + lane] = acc;
}

// ---------------- FC + softmax (warp per node) ---------------------------
__global__ void fc_softmax_kernel(const float* __restrict__ fw,
                                  const float* __restrict__ fb,
                                  float* __restrict__ out, int n) {
    int warp = (blockIdx.x * blockDim.x + threadIdx.x) >> 5;
    int lane = threadIdx.x & 31;
    if (warp >= n) return;
    const float* hr = g_agg + (size_t)warp * NH;

    float acc[NC];
#pragma unroll
    for (int c = 0; c < NC; c++) acc[c] = 0.0f;
#pragma unroll
    for (int kk = 0; kk < 4; kk++) {
        int k = lane + kk * 32;
        float hv = fmaxf(hr[k], 0.0f);
#pragma unroll
        for (int c = 0; c < NC; c++) acc[c] = fmaf(hv, __ldg(fw + k * NC + c), acc[c]);
    }
#pragma unroll
    for (int c = 0; c < NC; c++) {
#pragma unroll
        for (int off = 16; off; off >>= 1)
            acc[c] += __shfl_xor_sync(0xffffffffu, acc[c], off);
        acc[c] += fb[c];
    }
    float mx = acc[0];
#pragma unroll
    for (int c = 1; c < NC; c++) mx = fmaxf(mx, acc[c]);
    float ex[NC];
    float sum = 0.0f;
#pragma unroll
    for (int c = 0; c < NC; c++) { ex[c] = __expf(acc[c] - mx); sum += ex[c]; }
    float inv = 1.0f / sum;
    if (lane < NC) out[(size_t)warp * NC + lane] = ex[lane] * inv;
}

// ---------------- launch -------------------------------------------------
extern "C" void kernel_launch(void* const* d_in, const int* in_sizes, int n_in,
                              void* d_out, int out_size) {
    const float* x  = (const float*)d_in[0];
    const int*   ei = (const int*)d_in[1];
    const float* ew = (const float*)d_in[2];
    const float* W1 = (const float*)d_in[3];
    const float* b1 = (const float*)d_in[4];
    const float* W2 = (const float*)d_in[5];
    const float* b2 = (const float*)d_in[6];
    const float* W3 = (const float*)d_in[7];
    const float* b3 = (const float*)d_in[8];
    const float* fw = (const float*)d_in[9];
    const float* fb = (const float*)d_in[10];
    float* out = (float*)d_out;

    int N = in_sizes[0] / NF;
    int E = in_sizes[2];
    const int* src = ei;
    const int* dst = ei + E;

    float *hbuf, *aggbuf;
    cudaGetSymbolAddress((void**)&hbuf, g_h);
    cudaGetSymbolAddress((void**)&aggbuf, g_agg);

    const int T = 256;
    int gN = (N + T - 1) / T;
    int gE = (E + T - 1) / T;
    int gGa = (N * 32 + T - 1) / T;   // warp per node
    int gG = (N + 127) / 128;

    // precompute: degrees, dinv, CSR by dst (with fused coef)
    init_deg_kernel<<<gN, T>>>(N);
    accum_deg_kernel<<<gE, T>>>(dst, ew, E);
    dinv_kernel<<<gN, T>>>(N);
    scan_kernel<<<1, 1024>>>(N);
    fill_kernel<<<gE, T>>>(src, dst, ew, E);

    // layer 1
    sgemm_bn128<<<gG, T>>>(x, W1, hbuf, N, NF, 0);
    gather_kernel<<<gGa, T>>>(b1, N);
    // layer 2
    sgemm_bn128<<<gG, T>>>(aggbuf, W2, hbuf, N, NH, 1);
    gather_kernel<<<gGa, T>>>(b2, N);
    // layer 3
    sgemm_bn128<<<gG, T>>>(aggbuf, W3, hbuf, N, NH, 1);
    gather_kernel<<<gGa, T>>>(b3, N);

    // FC + softmax
    fc_softmax_kernel<<<gGa, T>>>(fw, fb, out, N);
}

// round 3
// speedup vs baseline: 1.4822x; 1.1052x over previous
#include <cuda_runtime.h>
#include <math.h>

#define NF 256
#define NH 128
#define NC 10
#define NMAX 50000
#define EMAX 800000
#define SCANB 1024

// Scratch
__device__ float g_h[(size_t)NMAX * NH];
__device__ float g_agg[(size_t)NMAX * NH];
__device__ float g_deg[NMAX];
__device__ float g_dinv[NMAX];
__device__ float g_selfc[NMAX];
__device__ int   g_cnt[NMAX];
__device__ int   g_pos[NMAX];
__device__ int   g_rowoff[NMAX + 1];
__device__ int   g_csr_src[EMAX];
__device__ float g_csr_coef[EMAX];
__device__ int   g_bsum[(NMAX + SCANB - 1) / SCANB];
__device__ int   g_boff[(NMAX + SCANB - 1) / SCANB];

// ---------------- f32x2 packed-FMA helpers -------------------------------
__device__ __forceinline__ unsigned long long pack2(float lo, float hi) {
    unsigned long long r;
    asm("mov.b64 %0,{%1,%2};" : "=l"(r) : "f"(lo), "f"(hi));
    return r;
}
__device__ __forceinline__ void fma2(unsigned long long& d, unsigned long long a,
                                     unsigned long long b) {
    asm("fma.rn.f32x2 %0,%1,%2,%0;" : "+l"(d) : "l"(a), "l"(b));
}
__device__ __forceinline__ float2 unpack2(unsigned long long v) {
    float2 r;
    asm("mov.b64 {%0,%1},%2;" : "=f"(r.x), "=f"(r.y) : "l"(v));
    return r;
}

// ---------------- degree / norm precompute -------------------------------
__global__ void init_deg_kernel(int n) {
    int i = blockIdx.x * blockDim.x + threadIdx.x;
    if (i < n) { g_deg[i] = 1.0f; g_cnt[i] = 0; }
}

__global__ void accum_deg_kernel(const int* __restrict__ dst,
                                 const float* __restrict__ ew, int E) {
    int e = blockIdx.x * blockDim.x + threadIdx.x;
    if (e < E) {
        int d = dst[e];
        atomicAdd(&g_deg[d], ew[e]);
        atomicAdd(&g_cnt[d], 1);
    }
}

__global__ void dinv_kernel(int n) {
    int i = blockIdx.x * blockDim.x + threadIdx.x;
    if (i < n) {
        float d = g_deg[i];
        float r = (d > 0.0f) ? rsqrtf(d) : 0.0f;
        g_dinv[i] = r;
        g_selfc[i] = r * r;
    }
}

// ---------------- 3-phase scan -------------------------------------------
// Phase 1: per-block (1024 elems) exclusive scan -> g_rowoff (local), g_bsum
__global__ __launch_bounds__(SCANB) void scan_phase1(int n) {
    __shared__ int warpsum[32];
    int tid = threadIdx.x, lane = tid & 31, wid = tid >> 5;
    int i = blockIdx.x * SCANB + tid;
    int v = (i < n) ? g_cnt[i] : 0;
    int x = v;
#pragma unroll
    for (int off = 1; off < 32; off <<= 1) {
        int y = __shfl_up_sync(0xffffffffu, x, off);
        if (lane >= off) x += y;
    }
    if (lane == 31) warpsum[wid] = x;
    __syncthreads();
    if (wid == 0) {
        int s = warpsum[lane];
#pragma unroll
        for (int off = 1; off < 32; off <<= 1) {
            int y = __shfl_up_sync(0xffffffffu, s, off);
            if (lane >= off) s += y;
        }
        warpsum[lane] = s;
    }
    __syncthreads();
    int woff = wid ? warpsum[wid - 1] : 0;
    if (i < n) g_rowoff[i] = x + woff - v;   // block-local exclusive
    if (tid == SCANB - 1) g_bsum[blockIdx.x] = x + woff;
}

// Phase 2: single block scans nb block sums (nb <= 64) -> g_boff, total
__global__ void scan_phase2(int nb, int n) {
    int lane = threadIdx.x & 31;
    int wid = threadIdx.x >> 5;
    __shared__ int ws[2];
    // nb <= 64: two warps
    int idx = threadIdx.x;
    int v = (idx < nb) ? g_bsum[idx] : 0;
    int x = v;
#pragma unroll
    for (int off = 1; off < 32; off <<= 1) {
        int y = __shfl_up_sync(0xffffffffu, x, off);
        if (lane >= off) x += y;
    }
    if (lane == 31) ws[wid] = x;
    __syncthreads();
    int add = (wid == 1) ? ws[0] : 0;
    if (idx < nb) g_boff[idx] = x + add - v;  // exclusive
    if (idx == nb - 1) g_rowoff[n] = x + add; // total edge count
}

// Phase 3: add block offsets, init g_pos
__global__ void scan_phase3(int n) {
    int i = blockIdx.x * blockDim.x + threadIdx.x;
    if (i < n) {
        int r = g_rowoff[i] + g_boff[i / SCANB];
        g_rowoff[i] = r;
        g_pos[i] = r;
    }
}

__global__ void fill_kernel(const int* __restrict__ src, const int* __restrict__ dst,
                            const float* __restrict__ ew, int E) {
    int e = blockIdx.x * blockDim.x + threadIdx.x;
    if (e < E) {
        int s = src[e], d = dst[e];
        int slot = atomicAdd(&g_pos[d], 1);
        g_csr_src[slot] = s;
        g_csr_coef[slot] = g_dinv[s] * ew[e] * g_dinv[d];
    }
}

// ---------------- SGEMM (f32x2, double-buffered smem) --------------------
__global__ __launch_bounds__(256) void sgemm_bn128(const float* __restrict__ A,
                                                   const float* __restrict__ B,
                                                   float* __restrict__ Cm,
                                                   int N, int K, int reluA) {
    __shared__ __align__(16) float As[2][8][128];
    __shared__ __align__(16) float Bs[2][8][128];

    int tid = threadIdx.x;
    int row0 = blockIdx.x * 128;
    int ty = tid >> 4;
    int tx = tid & 15;

    unsigned long long acc[8][4];
#pragma unroll
    for (int i = 0; i < 8; i++)
#pragma unroll
        for (int j = 0; j < 4; j++) acc[i][j] = 0ull;

    int aRow = tid >> 1;
    int aK4  = (tid & 1) * 4;
    int bK   = tid >> 5;
    int bCol = (tid & 31) * 4;
    int gr   = row0 + aRow;
    bool rowok = gr < N;
    const float* Aptr = A + (size_t)(rowok ? gr : 0) * K + aK4;

    // preload tile 0
    {
        float4 av = make_float4(0.f, 0.f, 0.f, 0.f);
        if (rowok) av = *reinterpret_cast<const float4*>(Aptr);
        if (reluA) {
            av.x = fmaxf(av.x, 0.f); av.y = fmaxf(av.y, 0.f);
            av.z = fmaxf(av.z, 0.f); av.w = fmaxf(av.w, 0.f);
        }
        As[0][aK4 + 0][aRow] = av.x;
        As[0][aK4 + 1][aRow] = av.y;
        As[0][aK4 + 2][aRow] = av.z;
        As[0][aK4 + 3][aRow] = av.w;
        float4 bv = *reinterpret_cast<const float4*>(B + (size_t)bK * 128 + bCol);
        *reinterpret_cast<float4*>(&Bs[0][bK][bCol]) = bv;
    }
    __syncthreads();

    int cur = 0;
    for (int kb = 0; kb < K; kb += 8) {
        float4 av, bv;
        bool more = (kb + 8) < K;
        if (more) {
            av = make_float4(0.f, 0.f, 0.f, 0.f);
            if (rowok) av = *reinterpret_cast<const float4*>(Aptr + kb + 8);
            if (reluA) {
                av.x = fmaxf(av.x, 0.f); av.y = fmaxf(av.y, 0.f);
                av.z = fmaxf(av.z, 0.f); av.w = fmaxf(av.w, 0.f);
            }
            bv = *reinterpret_cast<const float4*>(B + (size_t)(kb + 8 + bK) * 128 + bCol);
        }

#pragma unroll
        for (int k = 0; k < 8; k++) {
            float4 a0 = *reinterpret_cast<const float4*>(&As[cur][k][ty * 8]);
            float4 a1 = *reinterpret_cast<const float4*>(&As[cur][k][ty * 8 + 4]);
            ulonglong2 bp01 = *reinterpret_cast<const ulonglong2*>(&Bs[cur][k][tx * 8]);
            ulonglong2 bp23 = *reinterpret_cast<const ulonglong2*>(&Bs[cur][k][tx * 8 + 4]);
            float a[8] = {a0.x, a0.y, a0.z, a0.w, a1.x, a1.y, a1.z, a1.w};
#pragma unroll
            for (int i = 0; i < 8; i++) {
                unsigned long long ad = pack2(a[i], a[i]);
                fma2(acc[i][0], ad, bp01.x);
                fma2(acc[i][1], ad, bp01.y);
                fma2(acc[i][2], ad, bp23.x);
                fma2(acc[i][3], ad, bp23.y);
            }
        }

        if (more) {
            int nxt = cur ^ 1;
            As[nxt][aK4 + 0][aRow] = av.x;
            As[nxt][aK4 + 1][aRow] = av.y;
            As[nxt][aK4 + 2][aRow] = av.z;
            As[nxt][aK4 + 3][aRow] = av.w;
            *reinterpret_cast<float4*>(&Bs[nxt][bK][bCol]) = bv;
            __syncthreads();
            cur = nxt;
        }
    }

#pragma unroll
    for (int i = 0; i < 8; i++) {
        int grr = row0 + ty * 8 + i;
        if (grr < N) {
            float2 p0 = unpack2(acc[i][0]);
            float2 p1 = unpack2(acc[i][1]);
            float2 p2 = unpack2(acc[i][2]);
            float2 p3 = unpack2(acc[i][3]);
            float4 c0 = make_float4(p0.x, p0.y, p1.x, p1.y);
            float4 c1 = make_float4(p2.x, p2.y, p3.x, p3.y);
            *reinterpret_cast<float4*>(Cm + (size_t)grr * 128 + tx * 8) = c0;
            *reinterpret_cast<float4*>(Cm + (size_t)grr * 128 + tx * 8 + 4) = c1;
        }
    }
}

// ---------------- CSR gather aggregation (warp per node) -----------------
__global__ void gather_kernel(const float* __restrict__ b, int n) {
    int t = blockIdx.x * blockDim.x + threadIdx.x;
    int node = t >> 5;
    int lane = t & 31;
    if (node >= n) return;

    const float4* h4 = reinterpret_cast<const float4*>(g_h);
    float4 bv = reinterpret_cast<const float4*>(b)[lane];
    float sc = g_selfc[node];
    float4 hv = h4[(size_t)node * 32 + lane];
    float4 acc;
    acc.x = fmaf(hv.x, sc, bv.x);
    acc.y = fmaf(hv.y, sc, bv.y);
    acc.z = fmaf(hv.z, sc, bv.z);
    acc.w = fmaf(hv.w, sc, bv.w);

    int beg = g_rowoff[node];
    int end = g_rowoff[node + 1];
    int e = beg;
    for (; e + 1 < end; e += 2) {
        int s0 = __ldg(g_csr_src + e);
        int s1 = __ldg(g_csr_src + e + 1);
        float w0 = __ldg(g_csr_coef + e);
        float w1 = __ldg(g_csr_coef + e + 1);
        float4 v0 = h4[(size_t)s0 * 32 + lane];
        float4 v1 = h4[(size_t)s1 * 32 + lane];
        acc.x = fmaf(v0.x, w0, acc.x);
        acc.y = fmaf(v0.y, w0, acc.y);
        acc.z = fmaf(v0.z, w0, acc.z);
        acc.w = fmaf(v0.w, w0, acc.w);
        acc.x = fmaf(v1.x, w1, acc.x);
        acc.y = fmaf(v1.y, w1, acc.y);
        acc.z = fmaf(v1.z, w1, acc.z);
        acc.w = fmaf(v1.w, w1, acc.w);
    }
    if (e < end) {
        int s0 = __ldg(g_csr_src + e);
        float w0 = __ldg(g_csr_coef + e);
        float4 v0 = h4[(size_t)s0 * 32 + lane];
        acc.x = fmaf(v0.x, w0, acc.x);
        acc.y = fmaf(v0.y, w0, acc.y);
        acc.z = fmaf(v0.z, w0, acc.z);
        acc.w = fmaf(v0.w, w0, acc.w);
    }
    reinterpret_cast<float4*>(g_agg)[(size_t)node * 32 + lane] = acc;
}

// ---------------- FC + softmax (warp per node) ---------------------------
__global__ void fc_softmax_kernel(const float* __restrict__ fw,
                                  const float* __restrict__ fb,
                                  float* __restrict__ out, int n) {
    int warp = (blockIdx.x * blockDim.x + threadIdx.x) >> 5;
    int lane = threadIdx.x & 31;
    if (warp >= n) return;
    const float* hr = g_agg + (size_t)warp * NH;

    float acc[NC];
#pragma unroll
    for (int c = 0; c < NC; c++) acc[c] = 0.0f;
#pragma unroll
    for (int kk = 0; kk < 4; kk++) {
        int k = lane + kk * 32;
        float hv = fmaxf(hr[k], 0.0f);
#pragma unroll
        for (int c = 0; c < NC; c++) acc[c] = fmaf(hv, __ldg(fw + k * NC + c), acc[c]);
    }
#pragma unroll
    for (int c = 0; c < NC; c++) {
#pragma unroll
        for (int off = 16; off; off >>= 1)
            acc[c] += __shfl_xor_sync(0xffffffffu, acc[c], off);
        acc[c] += fb[c];
    }
    float mx = acc[0];
#pragma unroll
    for (int c = 1; c < NC; c++) mx = fmaxf(mx, acc[c]);
    float ex[NC];
    float sum = 0.0f;
#pragma unroll
    for (int c = 0; c < NC; c++) { ex[c] = __expf(acc[c] - mx); sum += ex[c]; }
    float inv = 1.0f / sum;
    if (lane < NC) out[(size_t)warp * NC + lane] = ex[lane] * inv;
}

// ---------------- launch -------------------------------------------------
extern "C" void kernel_launch(void* const* d_in, const int* in_sizes, int n_in,
                              void* d_out, int out_size) {
    const float* x  = (const float*)d_in[0];
    const int*   ei = (const int*)d_in[1];
    const float* ew = (const float*)d_in[2];
    const float* W1 = (const float*)d_in[3];
    const float* b1 = (const float*)d_in[4];
    const float* W2 = (const float*)d_in[5];
    const float* b2 = (const float*)d_in[6];
    const float* W3 = (const float*)d_in[7];
    const float* b3 = (const float*)d_in[8];
    const float* fw = (const float*)d_in[9];
    const float* fb = (const float*)d_in[10];
    float* out = (float*)d_out;

    int N = in_sizes[0] / NF;
    int E = in_sizes[2];
    const int* src = ei;
    const int* dst = ei + E;

    float *hbuf, *aggbuf;
    cudaGetSymbolAddress((void**)&hbuf, g_h);
    cudaGetSymbolAddress((void**)&aggbuf, g_agg);

    const int T = 256;
    int gN = (N + T - 1) / T;
    int gE = (E + T - 1) / T;
    int gGa = (N * 32 + T - 1) / T;
    int gG = (N + 127) / 128;
    int nb = (N + SCANB - 1) / SCANB;

    // precompute
    init_deg_kernel<<<gN, T>>>(N);
    accum_deg_kernel<<<gE, T>>>(dst, ew, E);
    dinv_kernel<<<gN, T>>>(N);
    scan_phase1<<<nb, SCANB>>>(N);
    scan_phase2<<<1, 64>>>(nb, N);
    scan_phase3<<<gN, T>>>(N);
    fill_kernel<<<gE, T>>>(src, dst, ew, E);

    // layer 1
    sgemm_bn128<<<gG, T>>>(x, W1, hbuf, N, NF, 0);
    gather_kernel<<<gGa, T>>>(b1, N);
    // layer 2
    sgemm_bn128<<<gG, T>>>(aggbuf, W2, hbuf, N, NH, 1);
    gather_kernel<<<gGa, T>>>(b2, N);
    // layer 3
    sgemm_bn128<<<gG, T>>>(aggbuf, W3, hbuf, N, NH, 1);
    gather_kernel<<<gGa, T>>>(b3, N);

    // FC + softmax
    fc_softmax_kernel<<<gGa, T>>>(fw, fb, out, N);
}

// round 5
// speedup vs baseline: 1.9493x; 1.3152x over previous
#include <cuda_runtime.h>
#include <math.h>
#include <stdint.h>

#define NF 256
#define NH 128
#define NC 10
#define NMAX 50000
#define EMAX 800000
#define SCANB 1024
#define KC 32      // K-chunk
#define AST 40     // smem row stride in b16 units (80B: 16B-aligned, conflict-free)

// Scratch
__device__ float g_h[(size_t)NMAX * NH];
__device__ float g_agg[(size_t)NMAX * NH];
__device__ float g_deg[NMAX];
__device__ float g_dinv[NMAX];
__device__ float g_selfc[NMAX];
__device__ int   g_cnt[NMAX];
__device__ int   g_pos[NMAX];
__device__ int   g_rowoff[NMAX + 1];
__device__ int   g_csr_src[EMAX];
__device__ float g_csr_coef[EMAX];
__device__ int   g_bsum[(NMAX + SCANB - 1) / SCANB];
__device__ int   g_boff[(NMAX + SCANB - 1) / SCANB];

// ---------------- helpers ------------------------------------------------
__device__ __forceinline__ uint32_t smem_u32(const void* p) {
    uint32_t a;
    asm("{ .reg .u64 t; cvta.to.shared.u64 t, %1; cvt.u32.u64 %0, t; }"
        : "=r"(a) : "l"(p));
    return a;
}
// pack two f32 -> bf16x2 (lo half = a, hi half = b)
__device__ __forceinline__ uint32_t pack_bf(float a, float b) {
    uint32_t r;
    asm("cvt.rn.bf16x2.f32 %0, %1, %2;" : "=r"(r) : "f"(b), "f"(a));
    return r;
}
__device__ __forceinline__ float bflo_f(uint32_t p) { return __uint_as_float(p << 16); }
__device__ __forceinline__ float bfhi_f(uint32_t p) { return __uint_as_float(p & 0xffff0000u); }

__device__ __forceinline__ void ldm4(uint32_t* r, uint32_t addr) {
    asm volatile("ldmatrix.sync.aligned.m8n8.x4.shared.b16 {%0,%1,%2,%3}, [%4];"
                 : "=r"(r[0]), "=r"(r[1]), "=r"(r[2]), "=r"(r[3]) : "r"(addr));
}
__device__ __forceinline__ void ldm2(uint32_t* r, uint32_t addr) {
    asm volatile("ldmatrix.sync.aligned.m8n8.x2.shared.b16 {%0,%1}, [%2];"
                 : "=r"(r[0]), "=r"(r[1]) : "r"(addr));
}
__device__ __forceinline__ void mma_bf16(float* d, const uint32_t* a, const uint32_t* b) {
    asm volatile(
        "mma.sync.aligned.m16n8k16.row.col.f32.bf16.bf16.f32 "
        "{%0,%1,%2,%3}, {%4,%5,%6,%7}, {%8,%9}, {%0,%1,%2,%3};"
        : "+f"(d[0]), "+f"(d[1]), "+f"(d[2]), "+f"(d[3])
        : "r"(a[0]), "r"(a[1]), "r"(a[2]), "r"(a[3]), "r"(b[0]), "r"(b[1]));
}

// ======================= tensor-core GEMM (mma.sync, bf16 split) =========
// C[N x 128] = A[N x K] @ W[K x 128]; fp32 accum; optional relu on A read.
__global__ __launch_bounds__(256, 1) void tc_gemm(const float* __restrict__ A,
                                                  const float* __restrict__ W,
                                                  float* __restrict__ Cm,
                                                  int N, int K, int reluA) {
    __shared__ __align__(16) uint16_t Ah[128 * AST];
    __shared__ __align__(16) uint16_t Al[128 * AST];
    __shared__ __align__(16) uint16_t Bh[128 * AST];
    __shared__ __align__(16) uint16_t Bl[128 * AST];

    int tid = threadIdx.x;
    int lane = tid & 31;
    int wid = tid >> 5;
    int wm = wid & 1;        // 2 m-blocks of 64 rows
    int wn = wid >> 1;       // 4 n-blocks of 32 cols
    int row0 = blockIdx.x * 128;

    float acc[4][4][4];      // [mt][nt][frag]
#pragma unroll
    for (int i = 0; i < 4; i++)
#pragma unroll
        for (int j = 0; j < 4; j++)
#pragma unroll
            for (int q = 0; q < 4; q++) acc[i][j][q] = 0.f;

    uint32_t aBase = smem_u32(Ah);
    uint32_t alBase = smem_u32(Al);
    uint32_t bBase = smem_u32(Bh);
    uint32_t blBase = smem_u32(Bl);

    // ldmatrix lane->address row/col components (precompute)
    int aLRow = lane & 15;          // row within 16-row tile
    int aLK = (lane >> 4) * 8;      // k offset 0/8
    int bLRow = lane & 7;           // n within 8
    int bLK = ((lane >> 3) & 1) * 8;

    for (int kb = 0; kb < K; kb += KC) {
        // ---- fill A: 128 rows x 32 k (hi/lo) ----
#pragma unroll
        for (int it = 0; it < 4; it++) {
            int idx = tid + it * 256;      // 0..1023 float4s
            int row = idx >> 3;
            int f4 = idx & 7;
            float4 v = make_float4(0.f, 0.f, 0.f, 0.f);
            int gr = row0 + row;
            if (gr < N)
                v = *reinterpret_cast<const float4*>(A + (size_t)gr * K + kb + f4 * 4);
            if (reluA) {
                v.x = fmaxf(v.x, 0.f); v.y = fmaxf(v.y, 0.f);
                v.z = fmaxf(v.z, 0.f); v.w = fmaxf(v.w, 0.f);
            }
            uint32_t h01 = pack_bf(v.x, v.y);
            uint32_t h23 = pack_bf(v.z, v.w);
            uint32_t l01 = pack_bf(v.x - bflo_f(h01), v.y - bfhi_f(h01));
            uint32_t l23 = pack_bf(v.z - bflo_f(h23), v.w - bfhi_f(h23));
            int o = row * AST + f4 * 4;    // b16 index, 8B aligned
            *reinterpret_cast<uint2*>(Ah + o) = make_uint2(h01, h23);
            *reinterpret_cast<uint2*>(Al + o) = make_uint2(l01, l23);
        }
        // ---- fill B: Bs[n][k] = W[kb+k][n], 128 n x 32 k (hi/lo) ----
#pragma unroll
        for (int it = 0; it < 8; it++) {
            int idx = tid + it * 256;      // 0..2047 (n, k-pair)
            int k2 = idx >> 7;
            int n = idx & 127;
            float v0 = W[(size_t)(kb + 2 * k2) * 128 + n];
            float v1 = W[(size_t)(kb + 2 * k2 + 1) * 128 + n];
            uint32_t h = pack_bf(v0, v1);
            uint32_t l = pack_bf(v0 - bflo_f(h), v1 - bfhi_f(h));
            int o = n * AST + k2 * 2;      // b16 index, 4B aligned
            *reinterpret_cast<uint32_t*>(Bh + o) = h;
            *reinterpret_cast<uint32_t*>(Bl + o) = l;
        }
        __syncthreads();

        // ---- mma over 2 k16 steps ----
#pragma unroll
        for (int ks = 0; ks < 2; ks++) {
            int k0 = ks * 16;
            uint32_t afh[4][4], afl[4][4];
#pragma unroll
            for (int mt = 0; mt < 4; mt++) {
                uint32_t off = (uint32_t)(((wm * 64 + mt * 16 + aLRow) * AST +
                                           k0 + aLK) * 2);
                ldm4(afh[mt], aBase + off);
                ldm4(afl[mt], alBase + off);
            }
            uint32_t bfh[4][2], bfl[4][2];
#pragma unroll
            for (int nt = 0; nt < 4; nt++) {
                uint32_t off = (uint32_t)(((wn * 32 + nt * 8 + bLRow) * AST +
                                           k0 + bLK) * 2);
                ldm2(bfh[nt], bBase + off);
                ldm2(bfl[nt], blBase + off);
            }
#pragma unroll
            for (int mt = 0; mt < 4; mt++)
#pragma unroll
                for (int nt = 0; nt < 4; nt++) {
                    mma_bf16(acc[mt][nt], afh[mt], bfh[nt]);
                    mma_bf16(acc[mt][nt], afh[mt], bfl[nt]);
                    mma_bf16(acc[mt][nt], afl[mt], bfh[nt]);
                }
        }
        __syncthreads();
    }

    // ---- epilogue: write acc to Cm ----
    int gid = lane >> 2;
    int tig = lane & 3;
#pragma unroll
    for (int mt = 0; mt < 4; mt++) {
        int r0 = row0 + wm * 64 + mt * 16 + gid;
        int r1 = r0 + 8;
#pragma unroll
        for (int nt = 0; nt < 4; nt++) {
            int col = wn * 32 + nt * 8 + tig * 2;
            if (r0 < N)
                *reinterpret_cast<float2*>(Cm + (size_t)r0 * 128 + col) =
                    make_float2(acc[mt][nt][0], acc[mt][nt][1]);
            if (r1 < N)
                *reinterpret_cast<float2*>(Cm + (size_t)r1 * 128 + col) =
                    make_float2(acc[mt][nt][2], acc[mt][nt][3]);
        }
    }
}

// ---------------- degree / norm precompute -------------------------------
__global__ void init_deg_kernel(int n) {
    int i = blockIdx.x * blockDim.x + threadIdx.x;
    if (i < n) { g_deg[i] = 1.0f; g_cnt[i] = 0; }
}

__global__ void accum_deg_kernel(const int* __restrict__ dst,
                                 const float* __restrict__ ew, int E) {
    int e = blockIdx.x * blockDim.x + threadIdx.x;
    if (e < E) {
        int d = dst[e];
        atomicAdd(&g_deg[d], ew[e]);
        atomicAdd(&g_cnt[d], 1);
    }
}

__global__ void dinv_kernel(int n) {
    int i = blockIdx.x * blockDim.x + threadIdx.x;
    if (i < n) {
        float d = g_deg[i];
        float r = (d > 0.0f) ? rsqrtf(d) : 0.0f;
        g_dinv[i] = r;
        g_selfc[i] = r * r;
    }
}

// ---------------- 3-phase scan -------------------------------------------
__global__ __launch_bounds__(SCANB) void scan_phase1(int n) {
    __shared__ int warpsum[32];
    int tid = threadIdx.x, lane = tid & 31, wid = tid >> 5;
    int i = blockIdx.x * SCANB + tid;
    int v = (i < n) ? g_cnt[i] : 0;
    int x = v;
#pragma unroll
    for (int off = 1; off < 32; off <<= 1) {
        int y = __shfl_up_sync(0xffffffffu, x, off);
        if (lane >= off) x += y;
    }
    if (lane == 31) warpsum[wid] = x;
    __syncthreads();
    if (wid == 0) {
        int s = warpsum[lane];
#pragma unroll
        for (int off = 1; off < 32; off <<= 1) {
            int y = __shfl_up_sync(0xffffffffu, s, off);
            if (lane >= off) s += y;
        }
        warpsum[lane] = s;
    }
    __syncthreads();
    int woff = wid ? warpsum[wid - 1] : 0;
    if (i < n) g_rowoff[i] = x + woff - v;
    if (tid == SCANB - 1) g_bsum[blockIdx.x] = x + woff;
}

__global__ void scan_phase2(int nb, int n) {
    int lane = threadIdx.x & 31;
    int wid = threadIdx.x >> 5;
    __shared__ int ws[2];
    int idx = threadIdx.x;
    int v = (idx < nb) ? g_bsum[idx] : 0;
    int x = v;
#pragma unroll
    for (int off = 1; off < 32; off <<= 1) {
        int y = __shfl_up_sync(0xffffffffu, x, off);
        if (lane >= off) x += y;
    }
    if (lane == 31) ws[wid] = x;
    __syncthreads();
    int add = (wid == 1) ? ws[0] : 0;
    if (idx < nb) g_boff[idx] = x + add - v;
    if (idx == nb - 1) g_rowoff[n] = x + add;
}

__global__ void scan_phase3(int n) {
    int i = blockIdx.x * blockDim.x + threadIdx.x;
    if (i < n) {
        int r = g_rowoff[i] + g_boff[i / SCANB];
        g_rowoff[i] = r;
        g_pos[i] = r;
    }
}

__global__ void fill_kernel(const int* __restrict__ src, const int* __restrict__ dst,
                            const float* __restrict__ ew, int E) {
    int e = blockIdx.x * blockDim.x + threadIdx.x;
    if (e < E) {
        int s = src[e], d = dst[e];
        int slot = atomicAdd(&g_pos[d], 1);
        g_csr_src[slot] = s;
        g_csr_coef[slot] = g_dinv[s] * ew[e] * g_dinv[d];
    }
}

// ---------------- CSR gather aggregation (warp per node) -----------------
__global__ void gather_kernel(const float* __restrict__ b, int n) {
    int t = blockIdx.x * blockDim.x + threadIdx.x;
    int node = t >> 5;
    int lane = t & 31;
    if (node >= n) return;

    const float4* h4 = reinterpret_cast<const float4*>(g_h);
    float4 bv = reinterpret_cast<const float4*>(b)[lane];
    float sc = g_selfc[node];
    float4 hv = h4[(size_t)node * 32 + lane];
    float4 acc;
    acc.x = fmaf(hv.x, sc, bv.x);
    acc.y = fmaf(hv.y, sc, bv.y);
    acc.z = fmaf(hv.z, sc, bv.z);
    acc.w = fmaf(hv.w, sc, bv.w);

    int beg = g_rowoff[node];
    int end = g_rowoff[node + 1];
    int e = beg;
    for (; e + 1 < end; e += 2) {
        int s0 = __ldg(g_csr_src + e);
        int s1 = __ldg(g_csr_src + e + 1);
        float w0 = __ldg(g_csr_coef + e);
        float w1 = __ldg(g_csr_coef + e + 1);
        float4 v0 = h4[(size_t)s0 * 32 + lane];
        float4 v1 = h4[(size_t)s1 * 32 + lane];
        acc.x = fmaf(v0.x, w0, acc.x);
        acc.y = fmaf(v0.y, w0, acc.y);
        acc.z = fmaf(v0.z, w0, acc.z);
        acc.w = fmaf(v0.w, w0, acc.w);
        acc.x = fmaf(v1.x, w1, acc.x);
        acc.y = fmaf(v1.y, w1, acc.y);
        acc.z = fmaf(v1.z, w1, acc.z);
        acc.w = fmaf(v1.w, w1, acc.w);
    }
    if (e < end) {
        int s0 = __ldg(g_csr_src + e);
        float w0 = __ldg(g_csr_coef + e);
        float4 v0 = h4[(size_t)s0 * 32 + lane];
        acc.x = fmaf(v0.x, w0, acc.x);
        acc.y = fmaf(v0.y, w0, acc.y);
        acc.z = fmaf(v0.z, w0, acc.z);
        acc.w = fmaf(v0.w, w0, acc.w);
    }
    reinterpret_cast<float4*>(g_agg)[(size_t)node * 32 + lane] = acc;
}

// ---------------- FC + softmax (warp per node) ---------------------------
__global__ void fc_softmax_kernel(const float* __restrict__ fw,
                                  const float* __restrict__ fb,
                                  float* __restrict__ out, int n) {
    int warp = (blockIdx.x * blockDim.x + threadIdx.x) >> 5;
    int lane = threadIdx.x & 31;
    if (warp >= n) return;
    const float* hr = g_agg + (size_t)warp * NH;

    float acc[NC];
#pragma unroll
    for (int c = 0; c < NC; c++) acc[c] = 0.0f;
#pragma unroll
    for (int kk = 0; kk < 4; kk++) {
        int k = lane + kk * 32;
        float hv = fmaxf(hr[k], 0.0f);
#pragma unroll
        for (int c = 0; c < NC; c++) acc[c] = fmaf(hv, __ldg(fw + k * NC + c), acc[c]);
    }
#pragma unroll
    for (int c = 0; c < NC; c++) {
#pragma unroll
        for (int off = 16; off; off >>= 1)
            acc[c] += __shfl_xor_sync(0xffffffffu, acc[c], off);
        acc[c] += fb[c];
    }
    float mx = acc[0];
#pragma unroll
    for (int c = 1; c < NC; c++) mx = fmaxf(mx, acc[c]);
    float ex[NC];
    float sum = 0.0f;
#pragma unroll
    for (int c = 0; c < NC; c++) { ex[c] = __expf(acc[c] - mx); sum += ex[c]; }
    float inv = 1.0f / sum;
    if (lane < NC) out[(size_t)warp * NC + lane] = ex[lane] * inv;
}

// ---------------- launch -------------------------------------------------
extern "C" void kernel_launch(void* const* d_in, const int* in_sizes, int n_in,
                              void* d_out, int out_size) {
    const float* x  = (const float*)d_in[0];
    const int*   ei = (const int*)d_in[1];
    const float* ew = (const float*)d_in[2];
    const float* W1 = (const float*)d_in[3];
    const float* b1 = (const float*)d_in[4];
    const float* W2 = (const float*)d_in[5];
    const float* b2 = (const float*)d_in[6];
    const float* W3 = (const float*)d_in[7];
    const float* b3 = (const float*)d_in[8];
    const float* fw = (const float*)d_in[9];
    const float* fb = (const float*)d_in[10];
    float* out = (float*)d_out;

    int N = in_sizes[0] / NF;
    int E = in_sizes[2];
    const int* src = ei;
    const int* dst = ei + E;

    float *hbuf, *aggbuf;
    cudaGetSymbolAddress((void**)&hbuf, g_h);
    cudaGetSymbolAddress((void**)&aggbuf, g_agg);

    const int T = 256;
    int gN = (N + T - 1) / T;
    int gE = (E + T - 1) / T;
    int gGa = (N * 32 + T - 1) / T;
    int gG = (N + 127) / 128;
    int nb = (N + SCANB - 1) / SCANB;

    // precompute
    init_deg_kernel<<<gN, T>>>(N);
    accum_deg_kernel<<<gE, T>>>(dst, ew, E);
    dinv_kernel<<<gN, T>>>(N);
    scan_phase1<<<nb, SCANB>>>(N);
    scan_phase2<<<1, 64>>>(nb, N);
    scan_phase3<<<gN, T>>>(N);
    fill_kernel<<<gE, T>>>(src, dst, ew, E);

    // layer 1
    tc_gemm<<<gG, T>>>(x, W1, hbuf, N, NF, 0);
    gather_kernel<<<gGa, T>>>(b1, N);
    // layer 2
    tc_gemm<<<gG, T>>>(aggbuf, W2, hbuf, N, NH, 1);
    gather_kernel<<<gGa, T>>>(b2, N);
    // layer 3
    tc_gemm<<<gG, T>>>(aggbuf, W3, hbuf, N, NH, 1);
    gather_kernel<<<gGa, T>>>(b3, N);

    // FC + softmax
    fc_softmax_kernel<<<gGa, T>>>(fw, fb, out, N);
}

// round 6
// speedup vs baseline: 2.0776x; 1.0658x over previous
#include <cuda_runtime.h>
#include <cuda_fp16.h>
#include <math.h>
#include <stdint.h>

#define NF 256
#define NH 128
#define NC 10
#define NMAX 50000
#define EMAX 800000
#define SCANB 1024
#define KC 32      // K-chunk
#define AST 40     // smem row stride in b16 units (80B: 16B-aligned, conflict-free)

// Scratch
__device__ __align__(16) __half g_h[(size_t)NMAX * NH];   // fp16 GEMM output
__device__ float g_agg[(size_t)NMAX * NH];
__device__ float g_deg[NMAX];
__device__ float g_dinv[NMAX];
__device__ float g_selfc[NMAX];
__device__ int   g_cnt[NMAX];
__device__ int   g_pos[NMAX];
__device__ int   g_rowoff[NMAX + 1];
__device__ int   g_csr_src[EMAX];
__device__ float g_csr_coef[EMAX];
__device__ int   g_bsum[(NMAX + SCANB - 1) / SCANB];
__device__ int   g_boff[(NMAX + SCANB - 1) / SCANB];

// ---------------- helpers ------------------------------------------------
__device__ __forceinline__ uint32_t smem_u32(const void* p) {
    uint32_t a;
    asm("{ .reg .u64 t; cvta.to.shared.u64 t, %1; cvt.u32.u64 %0, t; }"
        : "=r"(a) : "l"(p));
    return a;
}
// pack two f32 -> bf16x2 (lo half = a, hi half = b)
__device__ __forceinline__ uint32_t pack_bf(float a, float b) {
    uint32_t r;
    asm("cvt.rn.bf16x2.f32 %0, %1, %2;" : "=r"(r) : "f"(b), "f"(a));
    return r;
}
__device__ __forceinline__ float bflo_f(uint32_t p) { return __uint_as_float(p << 16); }
__device__ __forceinline__ float bfhi_f(uint32_t p) { return __uint_as_float(p & 0xffff0000u); }

__device__ __forceinline__ void ldm4(uint32_t* r, uint32_t addr) {
    asm volatile("ldmatrix.sync.aligned.m8n8.x4.shared.b16 {%0,%1,%2,%3}, [%4];"
                 : "=r"(r[0]), "=r"(r[1]), "=r"(r[2]), "=r"(r[3]) : "r"(addr));
}
__device__ __forceinline__ void ldm2(uint32_t* r, uint32_t addr) {
    asm volatile("ldmatrix.sync.aligned.m8n8.x2.shared.b16 {%0,%1}, [%2];"
                 : "=r"(r[0]), "=r"(r[1]) : "r"(addr));
}
__device__ __forceinline__ void mma_bf16(float* d, const uint32_t* a, const uint32_t* b) {
    asm volatile(
        "mma.sync.aligned.m16n8k16.row.col.f32.bf16.bf16.f32 "
        "{%0,%1,%2,%3}, {%4,%5,%6,%7}, {%8,%9}, {%0,%1,%2,%3};"
        : "+f"(d[0]), "+f"(d[1]), "+f"(d[2]), "+f"(d[3])
        : "r"(a[0]), "r"(a[1]), "r"(a[2]), "r"(a[3]), "r"(b[0]), "r"(b[1]));
}

// ======================= tensor-core GEMM (mma.sync, bf16 split) =========
// Cm[N x 128] (fp16) = A[N x K] (fp32) @ W[K x 128]; optional relu on A read.
__global__ __launch_bounds__(256, 1) void tc_gemm(const float* __restrict__ A,
                                                  const float* __restrict__ W,
                                                  __half* __restrict__ Cm,
                                                  int N, int K, int reluA) {
    __shared__ __align__(16) uint16_t Ah[128 * AST];
    __shared__ __align__(16) uint16_t Al[128 * AST];
    __shared__ __align__(16) uint16_t Bh[128 * AST];
    __shared__ __align__(16) uint16_t Bl[128 * AST];

    int tid = threadIdx.x;
    int lane = tid & 31;
    int wid = tid >> 5;
    int wm = wid & 1;
    int wn = wid >> 1;
    int row0 = blockIdx.x * 128;

    float acc[4][4][4];
#pragma unroll
    for (int i = 0; i < 4; i++)
#pragma unroll
        for (int j = 0; j < 4; j++)
#pragma unroll
            for (int q = 0; q < 4; q++) acc[i][j][q] = 0.f;

    uint32_t aBase = smem_u32(Ah);
    uint32_t alBase = smem_u32(Al);
    uint32_t bBase = smem_u32(Bh);
    uint32_t blBase = smem_u32(Bl);

    int aLRow = lane & 15;
    int aLK = (lane >> 4) * 8;
    int bLRow = lane & 7;
    int bLK = ((lane >> 3) & 1) * 8;

    for (int kb = 0; kb < K; kb += KC) {
        // ---- fill A ----
#pragma unroll
        for (int it = 0; it < 4; it++) {
            int idx = tid + it * 256;
            int row = idx >> 3;
            int f4 = idx & 7;
            float4 v = make_float4(0.f, 0.f, 0.f, 0.f);
            int gr = row0 + row;
            if (gr < N)
                v = *reinterpret_cast<const float4*>(A + (size_t)gr * K + kb + f4 * 4);
            if (reluA) {
                v.x = fmaxf(v.x, 0.f); v.y = fmaxf(v.y, 0.f);
                v.z = fmaxf(v.z, 0.f); v.w = fmaxf(v.w, 0.f);
            }
            uint32_t h01 = pack_bf(v.x, v.y);
            uint32_t h23 = pack_bf(v.z, v.w);
            uint32_t l01 = pack_bf(v.x - bflo_f(h01), v.y - bfhi_f(h01));
            uint32_t l23 = pack_bf(v.z - bflo_f(h23), v.w - bfhi_f(h23));
            int o = row * AST + f4 * 4;
            *reinterpret_cast<uint2*>(Ah + o) = make_uint2(h01, h23);
            *reinterpret_cast<uint2*>(Al + o) = make_uint2(l01, l23);
        }
        // ---- fill B ----
#pragma unroll
        for (int it = 0; it < 8; it++) {
            int idx = tid + it * 256;
            int k2 = idx >> 7;
            int n = idx & 127;
            float v0 = W[(size_t)(kb + 2 * k2) * 128 + n];
            float v1 = W[(size_t)(kb + 2 * k2 + 1) * 128 + n];
            uint32_t h = pack_bf(v0, v1);
            uint32_t l = pack_bf(v0 - bflo_f(h), v1 - bfhi_f(h));
            int o = n * AST + k2 * 2;
            *reinterpret_cast<uint32_t*>(Bh + o) = h;
            *reinterpret_cast<uint32_t*>(Bl + o) = l;
        }
        __syncthreads();

#pragma unroll
        for (int ks = 0; ks < 2; ks++) {
            int k0 = ks * 16;
            uint32_t afh[4][4], afl[4][4];
#pragma unroll
            for (int mt = 0; mt < 4; mt++) {
                uint32_t off = (uint32_t)(((wm * 64 + mt * 16 + aLRow) * AST +
                                           k0 + aLK) * 2);
                ldm4(afh[mt], aBase + off);
                ldm4(afl[mt], alBase + off);
            }
            uint32_t bfh[4][2], bfl[4][2];
#pragma unroll
            for (int nt = 0; nt < 4; nt++) {
                uint32_t off = (uint32_t)(((wn * 32 + nt * 8 + bLRow) * AST +
                                           k0 + bLK) * 2);
                ldm2(bfh[nt], bBase + off);
                ldm2(bfl[nt], blBase + off);
            }
#pragma unroll
            for (int mt = 0; mt < 4; mt++)
#pragma unroll
                for (int nt = 0; nt < 4; nt++) {
                    mma_bf16(acc[mt][nt], afh[mt], bfh[nt]);
                    mma_bf16(acc[mt][nt], afh[mt], bfl[nt]);
                    mma_bf16(acc[mt][nt], afl[mt], bfh[nt]);
                }
        }
        __syncthreads();
    }

    // ---- epilogue: write fp16 ----
    int gid = lane >> 2;
    int tig = lane & 3;
#pragma unroll
    for (int mt = 0; mt < 4; mt++) {
        int r0 = row0 + wm * 64 + mt * 16 + gid;
        int r1 = r0 + 8;
#pragma unroll
        for (int nt = 0; nt < 4; nt++) {
            int col = wn * 32 + nt * 8 + tig * 2;
            if (r0 < N) {
                __half2 p = __floats2half2_rn(acc[mt][nt][0], acc[mt][nt][1]);
                *reinterpret_cast<__half2*>(Cm + (size_t)r0 * 128 + col) = p;
            }
            if (r1 < N) {
                __half2 p = __floats2half2_rn(acc[mt][nt][2], acc[mt][nt][3]);
                *reinterpret_cast<__half2*>(Cm + (size_t)r1 * 128 + col) = p;
            }
        }
    }
}

// ---------------- degree / norm precompute -------------------------------
__global__ void init_deg_kernel(int n) {
    int i = blockIdx.x * blockDim.x + threadIdx.x;
    if (i < n) { g_deg[i] = 1.0f; g_cnt[i] = 0; }
}

__global__ void accum_deg_kernel(const int* __restrict__ dst,
                                 const float* __restrict__ ew, int E) {
    int e = blockIdx.x * blockDim.x + threadIdx.x;
    if (e < E) {
        int d = dst[e];
        atomicAdd(&g_deg[d], ew[e]);
        atomicAdd(&g_cnt[d], 1);
    }
}

__global__ void dinv_kernel(int n) {
    int i = blockIdx.x * blockDim.x + threadIdx.x;
    if (i < n) {
        float d = g_deg[i];
        float r = (d > 0.0f) ? rsqrtf(d) : 0.0f;
        g_dinv[i] = r;
        g_selfc[i] = r * r;
    }
}

// ---------------- 3-phase scan -------------------------------------------
__global__ __launch_bounds__(SCANB) void scan_phase1(int n) {
    __shared__ int warpsum[32];
    int tid = threadIdx.x, lane = tid & 31, wid = tid >> 5;
    int i = blockIdx.x * SCANB + tid;
    int v = (i < n) ? g_cnt[i] : 0;
    int x = v;
#pragma unroll
    for (int off = 1; off < 32; off <<= 1) {
        int y = __shfl_up_sync(0xffffffffu, x, off);
        if (lane >= off) x += y;
    }
    if (lane == 31) warpsum[wid] = x;
    __syncthreads();
    if (wid == 0) {
        int s = warpsum[lane];
#pragma unroll
        for (int off = 1; off < 32; off <<= 1) {
            int y = __shfl_up_sync(0xffffffffu, s, off);
            if (lane >= off) s += y;
        }
        warpsum[lane] = s;
    }
    __syncthreads();
    int woff = wid ? warpsum[wid - 1] : 0;
    if (i < n) g_rowoff[i] = x + woff - v;
    if (tid == SCANB - 1) g_bsum[blockIdx.x] = x + woff;
}

__global__ void scan_phase2(int nb, int n) {
    int lane = threadIdx.x & 31;
    int wid = threadIdx.x >> 5;
    __shared__ int ws[2];
    int idx = threadIdx.x;
    int v = (idx < nb) ? g_bsum[idx] : 0;
    int x = v;
#pragma unroll
    for (int off = 1; off < 32; off <<= 1) {
        int y = __shfl_up_sync(0xffffffffu, x, off);
        if (lane >= off) x += y;
    }
    if (lane == 31) ws[wid] = x;
    __syncthreads();
    int add = (wid == 1) ? ws[0] : 0;
    if (idx < nb) g_boff[idx] = x + add - v;
    if (idx == nb - 1) g_rowoff[n] = x + add;
}

__global__ void scan_phase3(int n) {
    int i = blockIdx.x * blockDim.x + threadIdx.x;
    if (i < n) {
        int r = g_rowoff[i] + g_boff[i / SCANB];
        g_rowoff[i] = r;
        g_pos[i] = r;
    }
}

__global__ void fill_kernel(const int* __restrict__ src, const int* __restrict__ dst,
                            const float* __restrict__ ew, int E) {
    int e = blockIdx.x * blockDim.x + threadIdx.x;
    if (e < E) {
        int s = src[e], d = dst[e];
        int slot = atomicAdd(&g_pos[d], 1);
        g_csr_src[slot] = s;
        g_csr_coef[slot] = g_dinv[s] * ew[e] * g_dinv[d];
    }
}

// ---------------- CSR gather aggregation (warp per node, fp16 h) ---------
// lane covers 4 columns: reads uint2 = 4 halves (8B); 32 lanes = 128 cols.
__global__ void gather_kernel(const float* __restrict__ b, int n) {
    int t = blockIdx.x * blockDim.x + threadIdx.x;
    int node = t >> 5;
    int lane = t & 31;
    if (node >= n) return;

    const __half2* h2 = reinterpret_cast<const __half2*>(g_h);
    // lane's 2 half2 slots within a row of 64 half2
    float4 bv = reinterpret_cast<const float4*>(b)[lane];
    float sc = g_selfc[node];

    float4 acc;
    {
        __half2 a0 = h2[(size_t)node * 64 + 2 * lane];
        __half2 a1 = h2[(size_t)node * 64 + 2 * lane + 1];
        float2 f0 = __half22float2(a0);
        float2 f1 = __half22float2(a1);
        acc.x = fmaf(f0.x, sc, bv.x);
        acc.y = fmaf(f0.y, sc, bv.y);
        acc.z = fmaf(f1.x, sc, bv.z);
        acc.w = fmaf(f1.y, sc, bv.w);
    }

    int beg = g_rowoff[node];
    int end = g_rowoff[node + 1];
    int e = beg;
    for (; e + 1 < end; e += 2) {
        int s0 = __ldg(g_csr_src + e);
        int s1 = __ldg(g_csr_src + e + 1);
        float w0 = __ldg(g_csr_coef + e);
        float w1 = __ldg(g_csr_coef + e + 1);
        __half2 a0 = h2[(size_t)s0 * 64 + 2 * lane];
        __half2 a1 = h2[(size_t)s0 * 64 + 2 * lane + 1];
        __half2 c0 = h2[(size_t)s1 * 64 + 2 * lane];
        __half2 c1 = h2[(size_t)s1 * 64 + 2 * lane + 1];
        float2 f0 = __half22float2(a0);
        float2 f1 = __half22float2(a1);
        float2 g0 = __half22float2(c0);
        float2 g1 = __half22float2(c1);
        acc.x = fmaf(f0.x, w0, acc.x);
        acc.y = fmaf(f0.y, w0, acc.y);
        acc.z = fmaf(f1.x, w0, acc.z);
        acc.w = fmaf(f1.y, w0, acc.w);
        acc.x = fmaf(g0.x, w1, acc.x);
        acc.y = fmaf(g0.y, w1, acc.y);
        acc.z = fmaf(g1.x, w1, acc.z);
        acc.w = fmaf(g1.y, w1, acc.w);
    }
    if (e < end) {
        int s0 = __ldg(g_csr_src + e);
        float w0 = __ldg(g_csr_coef + e);
        __half2 a0 = h2[(size_t)s0 * 64 + 2 * lane];
        __half2 a1 = h2[(size_t)s0 * 64 + 2 * lane + 1];
        float2 f0 = __half22float2(a0);
        float2 f1 = __half22float2(a1);
        acc.x = fmaf(f0.x, w0, acc.x);
        acc.y = fmaf(f0.y, w0, acc.y);
        acc.z = fmaf(f1.x, w0, acc.z);
        acc.w = fmaf(f1.y, w0, acc.w);
    }
    reinterpret_cast<float4*>(g_agg)[(size_t)node * 32 + lane] = acc;
}

// ---------------- FC + softmax (warp per node) ---------------------------
__global__ void fc_softmax_kernel(const float* __restrict__ fw,
                                  const float* __restrict__ fb,
                                  float* __restrict__ out, int n) {
    int warp = (blockIdx.x * blockDim.x + threadIdx.x) >> 5;
    int lane = threadIdx.x & 31;
    if (warp >= n) return;
    const float* hr = g_agg + (size_t)warp * NH;

    float acc[NC];
#pragma unroll
    for (int c = 0; c < NC; c++) acc[c] = 0.0f;
#pragma unroll
    for (int kk = 0; kk < 4; kk++) {
        int k = lane + kk * 32;
        float hv = fmaxf(hr[k], 0.0f);
#pragma unroll
        for (int c = 0; c < NC; c++) acc[c] = fmaf(hv, __ldg(fw + k * NC + c), acc[c]);
    }
#pragma unroll
    for (int c = 0; c < NC; c++) {
#pragma unroll
        for (int off = 16; off; off >>= 1)
            acc[c] += __shfl_xor_sync(0xffffffffu, acc[c], off);
        acc[c] += fb[c];
    }
    float mx = acc[0];
#pragma unroll
    for (int c = 1; c < NC; c++) mx = fmaxf(mx, acc[c]);
    float ex[NC];
    float sum = 0.0f;
#pragma unroll
    for (int c = 0; c < NC; c++) { ex[c] = __expf(acc[c] - mx); sum += ex[c]; }
    float inv = 1.0f / sum;
    if (lane < NC) out[(size_t)warp * NC + lane] = ex[lane] * inv;
}

// ---------------- launch -------------------------------------------------
extern "C" void kernel_launch(void* const* d_in, const int* in_sizes, int n_in,
                              void* d_out, int out_size) {
    const float* x  = (const float*)d_in[0];
    const int*   ei = (const int*)d_in[1];
    const float* ew = (const float*)d_in[2];
    const float* W1 = (const float*)d_in[3];
    const float* b1 = (const float*)d_in[4];
    const float* W2 = (const float*)d_in[5];
    const float* b2 = (const float*)d_in[6];
    const float* W3 = (const float*)d_in[7];
    const float* b3 = (const float*)d_in[8];
    const float* fw = (const float*)d_in[9];
    const float* fb = (const float*)d_in[10];
    float* out = (float*)d_out;

    int N = in_sizes[0] / NF;
    int E = in_sizes[2];
    const int* src = ei;
    const int* dst = ei + E;

    __half* hbuf;
    float* aggbuf;
    cudaGetSymbolAddress((void**)&hbuf, g_h);
    cudaGetSymbolAddress((void**)&aggbuf, g_agg);

    const int T = 256;
    int gN = (N + T - 1) / T;
    int gE = (E + T - 1) / T;
    int gGa = (N * 32 + T - 1) / T;
    int gG = (N + 127) / 128;
    int nb = (N + SCANB - 1) / SCANB;

    // precompute
    init_deg_kernel<<<gN, T>>>(N);
    accum_deg_kernel<<<gE, T>>>(dst, ew, E);
    dinv_kernel<<<gN, T>>>(N);
    scan_phase1<<<nb, SCANB>>>(N);
    scan_phase2<<<1, 64>>>(nb, N);
    scan_phase3<<<gN, T>>>(N);
    fill_kernel<<<gE, T>>>(src, dst, ew, E);

    // layer 1
    tc_gemm<<<gG, T>>>(x, W1, hbuf, N, NF, 0);
    gather_kernel<<<gGa, T>>>(b1, N);
    // layer 2
    tc_gemm<<<gG, T>>>(aggbuf, W2, hbuf, N, NH, 1);
    gather_kernel<<<gGa, T>>>(b2, N);
    // layer 3
    tc_gemm<<<gG, T>>>(aggbuf, W3, hbuf, N, NH, 1);
    gather_kernel<<<gGa, T>>>(b3, N);

    // FC + softmax
    fc_softmax_kernel<<<gGa, T>>>(fw, fb, out, N);
}